// round 5
// baseline (speedup 1.0000x reference)
#include <cuda_runtime.h>
#include <cuda_bf16.h>
#include <math.h>

#define NN 1024
#define H 256

typedef unsigned long long u64;

// ---------------- f32x2 packed helpers (sm_103a) ----------------------------
__device__ __forceinline__ u64 add2(u64 a, u64 b) {
    u64 r; asm("add.rn.f32x2 %0,%1,%2;" : "=l"(r) : "l"(a), "l"(b)); return r;
}
__device__ __forceinline__ void fma2(u64& d, u64 a, u64 b) {
    asm("fma.rn.f32x2 %0,%1,%2,%0;" : "+l"(d) : "l"(a), "l"(b));
}
__device__ __forceinline__ float2 unpack2(u64 v) {
    float2 r; asm("mov.b64 {%0,%1},%2;" : "=f"(r.x), "=f"(r.y) : "l"(v)); return r;
}

// ---------------- cp.async helpers ------------------------------------------
__device__ __forceinline__ void cp8(void* dst_smem, const void* src) {
    unsigned d = (unsigned)__cvta_generic_to_shared(dst_smem);
    asm volatile("cp.async.ca.shared.global [%0], [%1], 8;" :: "r"(d), "l"(src));
}
__device__ __forceinline__ void cp_commit() {
    asm volatile("cp.async.commit_group;" ::: "memory");
}
template <int N>
__device__ __forceinline__ void cp_wait() {
    asm volatile("cp.async.wait_group %0;" :: "n"(N) : "memory");
}

// ---------------- scratch ----------------------------------------------------
__device__ float g_P[8 * NN * H];
__device__ float g_Q[2 * NN * H];
__device__ float g_X1[NN * H];
__device__ float g_X2[NN * H];
__device__ float g_hij[2 * NN * H];  // plane 0 = hi, plane 1 = hjb
__device__ float g_E[NN * NN];
__device__ float g_S[256 * 512];
__device__ float g_sc1[H], g_sh1[H];
__device__ float g_sc2[H], g_sh2[H];
__device__ float g_ci[NN], g_dj[NN];
__device__ float g_ws[NN];

// ---------------- GEMM: tile 32x64, 128 thr, f32x2 K-packed -----------------
// DUAL:  z selects B half (B + z*H*H); full K; output plane z; bias on z==1.
// else:  z selects K chunk (len KS);  output plane z.
// BNA: A transformed on load: relu(fma(a, bnsc[k], bnsh[k]))   (k-indexed)
// BNB: B transformed on load: relu(fma(b, bnsc[col], bnsh[col])) (col-indexed)
template <bool DUAL, bool BNA, bool BNB>
__global__ __launch_bounds__(128) void gemm_k(
    const float* __restrict__ A, const float* __restrict__ B,
    float* __restrict__ C0, int K, int KS,
    const float* __restrict__ bias,
    const float* __restrict__ bnsc, const float* __restrict__ bnsh) {
    __shared__ float As[2][32][18];
    __shared__ float Bs[2][64][18];

    const int t = threadIdx.x;
    const int tx = t & 15;
    const int ty = t >> 4;
    const int I = blockIdx.y * 32;
    const int J = blockIdx.x * 64;
    const int z = blockIdx.z;

    const float* Bp = DUAL ? (B + (size_t)z * H * H) : B;
    const int kbase = DUAL ? 0 : z * KS;
    float* Cp = C0 + (size_t)z * NN * H;

    float scvB = 0.f, shvB = 0.f;
    if (BNB) {
        const int col = J + (t & 63);
        scvB = bnsc[col];
        shvB = bnsh[col];
    }

    const int kiters = KS >> 4;
    float ra[4], rb[8];

    auto loadA = [&](int kt) {
        const int c = t & 15;
        const int kc = kbase + kt * 16 + c;
        float scv = 0.f, shv = 0.f;
        if (BNA) { scv = bnsc[kc]; shv = bnsh[kc]; }
#pragma unroll
        for (int e = 0; e < 4; e++) {
            int r = (t >> 4) + e * 8;
            float v = A[(size_t)(I + r) * K + kc];
            if (BNA) v = fmaxf(fmaf(v, scv, shv), 0.f);
            ra[e] = v;
        }
    };
    auto loadB = [&](int kt) {
        const int c = t & 63;
        const int r0 = t >> 6;
#pragma unroll
        for (int e = 0; e < 8; e++) {
            int r = r0 + e * 2;
            float v = Bp[(size_t)(kbase + kt * 16 + r) * H + J + c];
            if (BNB) v = fmaxf(fmaf(v, scvB, shvB), 0.f);
            rb[e] = v;
        }
    };
    auto stageS = [&](int buf) {
        const int ca = t & 15;
#pragma unroll
        for (int e = 0; e < 4; e++) As[buf][(t >> 4) + e * 8][ca] = ra[e];
        const int cb = t & 63;
        const int r0 = t >> 6;
#pragma unroll
        for (int e = 0; e < 8; e++) Bs[buf][cb][r0 + e * 2] = rb[e];
    };

    u64 acc[4][4];
#pragma unroll
    for (int m = 0; m < 4; m++)
#pragma unroll
        for (int n = 0; n < 4; n++) acc[m][n] = 0ull;

    loadA(0); loadB(0);
    stageS(0);
    __syncthreads();

    for (int kt = 0; kt < kiters; kt++) {
        const int buf = kt & 1;
        if (kt + 1 < kiters) { loadA(kt + 1); loadB(kt + 1); }
#pragma unroll
        for (int kp = 0; kp < 8; kp++) {
            u64 aP[4], bP[4];
#pragma unroll
            for (int m = 0; m < 4; m++)
                aP[m] = *(const u64*)&As[buf][ty * 4 + m][kp * 2];
#pragma unroll
            for (int n = 0; n < 4; n++)
                bP[n] = *(const u64*)&Bs[buf][tx + n * 16][kp * 2];
#pragma unroll
            for (int m = 0; m < 4; m++)
#pragma unroll
                for (int n = 0; n < 4; n++) fma2(acc[m][n], aP[m], bP[n]);
        }
        if (kt + 1 < kiters) {
            stageS(buf ^ 1);
            __syncthreads();
        }
    }

#pragma unroll
    for (int m = 0; m < 4; m++) {
        const int row = I + ty * 4 + m;
#pragma unroll
        for (int n = 0; n < 4; n++) {
            const int col = J + tx + n * 16;
            float2 p = unpack2(acc[m][n]);
            float v = p.x + p.y;
            if (DUAL && z == 1) v += bias[col];
            Cp[(size_t)row * H + col] = v;
        }
    }
}

// ---------------- BN stats phase1: X = sum(P)+bias, partial s/sq ------------
template <int NP>
__global__ void stats_phase1(const float* __restrict__ P, const float* __restrict__ bias,
                             float* __restrict__ X, float* __restrict__ S) {
    const int t = threadIdx.x;
    const int c4 = t & 63;
    const int rg = t >> 6;
    const int row = blockIdx.x * 4 + rg;
    float4 bv = ((const float4*)bias)[c4];
    constexpr size_t Q = NN * H / 4;
    size_t idx = (size_t)row * 64 + c4;
    float4 v = bv;
#pragma unroll
    for (int p = 0; p < NP; p++) {
        float4 a = ((const float4*)P)[(size_t)p * Q + idx];
        v.x += a.x; v.y += a.y; v.z += a.z; v.w += a.w;
    }
    ((float4*)X)[idx] = v;
    float4 q;
    q.x = v.x * v.x; q.y = v.y * v.y; q.z = v.z * v.z; q.w = v.w * v.w;
    __shared__ float4 sm[4][64], qm[4][64];
    sm[rg][c4] = v;
    qm[rg][c4] = q;
    __syncthreads();
    if (t < 64) {
        float4 S4 = make_float4(0.f, 0.f, 0.f, 0.f);
        float4 Q4 = make_float4(0.f, 0.f, 0.f, 0.f);
#pragma unroll
        for (int p = 0; p < 4; p++) {
            float4 a = sm[p][t], b = qm[p][t];
            S4.x += a.x; S4.y += a.y; S4.z += a.z; S4.w += a.w;
            Q4.x += b.x; Q4.y += b.y; Q4.z += b.z; Q4.w += b.w;
        }
        ((float4*)S)[blockIdx.x * 128 + t] = S4;
        ((float4*)S)[blockIdx.x * 128 + 64 + t] = Q4;
    }
}

// ---------------- BN stats phase2 -------------------------------------------
__global__ void stats_phase2(const float* __restrict__ S, const float* __restrict__ g,
                             const float* __restrict__ bt, float* __restrict__ sc,
                             float* __restrict__ sh) {
    const int t = threadIdx.x;
    const int c = blockIdx.x * 32 + (t & 31);
    const int pg = t >> 5;
    float s = 0.f, q = 0.f;
#pragma unroll
    for (int p = pg; p < 256; p += 8) {
        s += S[p * 512 + c];
        q += S[p * 512 + 256 + c];
    }
    __shared__ float sm[8][32], qm[8][32];
    sm[pg][t & 31] = s;
    qm[pg][t & 31] = q;
    __syncthreads();
    if (t < 32) {
        float S_ = 0.f, Q_ = 0.f;
#pragma unroll
        for (int p = 0; p < 8; p++) { S_ += sm[p][t]; Q_ += qm[p][t]; }
        const int col = blockIdx.x * 32 + t;
        float m = S_ * (1.f / NN);
        float var = Q_ * (1.f / NN) - m * m;
        float scv = g[col] * rsqrtf(var + 1e-5f);
        sc[col] = scv;
        sh[col] = bt[col] - m * scv;
    }
}

// ---------------- ci/dj GEMVs: 0.5 * (rows of hij @ We2) ---------------------
__global__ void cidj_kernel(const float* __restrict__ hij, const float* __restrict__ We2,
                            float* __restrict__ ci, float* __restrict__ dj) {
    const int gt = blockIdx.x * 256 + threadIdx.x;
    const int w = gt >> 5;  // 0..2047 (row in hij, planes concat)
    const int lane = gt & 31;
    float s = 0.f;
#pragma unroll
    for (int e = 0; e < 8; e++) {
        int c = lane + e * 32;
        s = fmaf(hij[(size_t)w * H + c], We2[c], s);
    }
#pragma unroll
    for (int o = 16; o > 0; o >>= 1) s += __shfl_xor_sync(~0u, s, o);
    if (lane == 0) {
        if (w < NN) ci[w] = 0.5f * s;
        else dj[w - NN] = 0.5f * s;
    }
}

// ---------------- Edge kernel: 32x128 tile, swizzled cp.async ---------------
// logit = 0.5*sum_h w*|a+b| + ci[i] + dj[j] + bwe2
// smem: float2[row][16] per 32-h chunk; element (r,c2) stored at c2^(r&15).
__global__ __launch_bounds__(128) void edge_kernel(
    const float* __restrict__ hi, const float* __restrict__ hjb,
    const float* __restrict__ We2, const float* __restrict__ bwe2,
    const int* __restrict__ labels,
    const float* __restrict__ ci, const float* __restrict__ dj,
    float* __restrict__ E) {
    __shared__ float2 sa[2][32][16];
    __shared__ float2 sb[2][128][16];
    __shared__ float sw[256];
    __shared__ int li[32], lj[128];
    __shared__ float sci[32], sdj[128];

    const int t = threadIdx.x;
    const int tx = t & 15;
    const int ty = t >> 4;  // 0..7
    const int I = blockIdx.y * 32;
    const int J = blockIdx.x * 128;

    sw[t] = 0.5f * We2[t];
    sw[t + 128] = 0.5f * We2[t + 128];
    lj[t] = labels[J + t];
    sdj[t] = dj[J + t];
    if (t < 32) { li[t] = labels[I + t]; sci[t] = ci[I + t]; }

    auto stage = [&](int c) {
        const int buf = c & 1;
        const int hoff = c * 32;
#pragma unroll
        for (int k = 0; k < 20; k++) {
            int p = t + k * 128;  // 0..2559
            if (p < 512) {
                int r = p >> 4, c2 = p & 15;
                cp8(&sa[buf][r][c2 ^ (r & 15)],
                    hi + (size_t)(I + r) * H + hoff + c2 * 2);
            } else {
                int q = p - 512;
                int r = q >> 4, c2 = q & 15;
                cp8(&sb[buf][r][c2 ^ (r & 15)],
                    hjb + (size_t)(J + r) * H + hoff + c2 * 2);
            }
        }
    };

    u64 acc[4][8];
#pragma unroll
    for (int m = 0; m < 4; m++)
#pragma unroll
        for (int n = 0; n < 8; n++) acc[m][n] = 0ull;

    stage(0);
    cp_commit();

    for (int c = 0; c < 8; c++) {
        if (c < 7) {
            stage(c + 1);
            cp_commit();
            cp_wait<1>();
        } else {
            cp_wait<0>();
        }
        __syncthreads();
        const int buf = c & 1;
        const float* swc = &sw[c * 32];
#pragma unroll
        for (int hp = 0; hp < 16; hp++) {
            u64 w = *(const u64*)&swc[hp * 2];
            u64 aP[4], bP[8];
#pragma unroll
            for (int m = 0; m < 4; m++) {
                const int r = ty + m * 8;
                aP[m] = *(const u64*)&sa[buf][r][hp ^ (r & 15)];
            }
#pragma unroll
            for (int n = 0; n < 8; n++)
                bP[n] = *(const u64*)&sb[buf][tx + n * 16][hp ^ tx];
#pragma unroll
            for (int m = 0; m < 4; m++)
#pragma unroll
                for (int n = 0; n < 8; n++) {
                    u64 s = add2(aP[m], bP[n]) & 0x7FFFFFFF7FFFFFFFull;
                    fma2(acc[m][n], s, w);
                }
        }
        __syncthreads();
    }

    const float bw = bwe2[0];
#pragma unroll
    for (int m = 0; m < 4; m++) {
        const int il = ty + m * 8;
        const int i = I + il;
        const int la = li[il];
        const float cv = sci[il] + bw;
#pragma unroll
        for (int n = 0; n < 8; n++) {
            const int jl = tx + n * 16;
            const int j = J + jl;
            float2 p = unpack2(acc[m][n]);
            float logit = p.x + p.y + cv + sdj[jl];
            float e = (la == lj[jl] && i != j)
                          ? 1.f / (1.f + __expf(-logit)) : 0.f;
            E[(size_t)i * NN + j] = e;
        }
    }
}

// ---------------- deterministic row sum of E --------------------------------
__global__ void row_sum(const float* __restrict__ E, float* __restrict__ wsum) {
    const int i = blockIdx.x;
    const int t = threadIdx.x;
    float4 v = ((const float4*)(E + (size_t)i * NN))[t];
    float s = v.x + v.y + v.z + v.w;
#pragma unroll
    for (int o = 16; o > 0; o >>= 1) s += __shfl_xor_sync(~0u, s, o);
    __shared__ float sm[8];
    if ((t & 31) == 0) sm[t >> 5] = s;
    __syncthreads();
    if (t == 0) {
        float S = 0.f;
#pragma unroll
        for (int k = 0; k < 8; k++) S += sm[k];
        wsum[i] = S;
    }
}

// ---------------- final: out = di + sum(P)/wsum (di inline from X2) ---------
__global__ void reduce_epi(const float* __restrict__ P, const float* __restrict__ X2,
                           const float* __restrict__ sc, const float* __restrict__ sh,
                           const float* __restrict__ ws, float* __restrict__ out) {
    const int idx = blockIdx.x * 256 + threadIdx.x;
    const int row = idx >> 6;
    const int c4 = idx & 63;
    float w = ws[row];
    float inv = w > 0.f ? 1.f / w : 0.f;
    constexpr size_t Q = NN * H / 4;
    float4 s = make_float4(0.f, 0.f, 0.f, 0.f);
#pragma unroll
    for (int p = 0; p < 8; p++) {
        float4 a = ((const float4*)P)[p * Q + idx];
        s.x += a.x; s.y += a.y; s.z += a.z; s.w += a.w;
    }
    float4 x = ((const float4*)X2)[idx];
    float4 scv = ((const float4*)sc)[c4];
    float4 shv = ((const float4*)sh)[c4];
    float4 d;
    d.x = fmaxf(fmaf(x.x, scv.x, shv.x), 0.f);
    d.y = fmaxf(fmaf(x.y, scv.y, shv.y), 0.f);
    d.z = fmaxf(fmaf(x.z, scv.z, shv.z), 0.f);
    d.w = fmaxf(fmaf(x.w, scv.w, shv.w), 0.f);
    float4 o;
    o.x = fmaf(s.x, inv, d.x);
    o.y = fmaf(s.y, inv, d.y);
    o.z = fmaf(s.z, inv, d.z);
    o.w = fmaf(s.w, inv, d.w);
    ((float4*)out)[idx] = o;
}

// ---------------- launch -----------------------------------------------------
extern "C" void kernel_launch(void* const* d_in, const int* in_sizes, int n_in,
                              void* d_out, int out_size) {
    const float* features = (const float*)d_in[0];
    const int* labels = (const int*)d_in[1];
    const float* W1 = (const float*)d_in[2];
    const float* b1 = (const float*)d_in[3];
    const float* g1 = (const float*)d_in[4];
    const float* bt1 = (const float*)d_in[5];
    const float* W2 = (const float*)d_in[6];
    const float* b2 = (const float*)d_in[7];
    const float* g2 = (const float*)d_in[8];
    const float* bt2 = (const float*)d_in[9];
    const float* We1 = (const float*)d_in[10];
    const float* bwe1 = (const float*)d_in[11];
    const float* We2 = (const float*)d_in[12];
    const float* bwe2 = (const float*)d_in[13];
    float* out = (float*)d_out;

    void *pP, *pQ, *pX1, *pX2, *phij, *pE, *pS, *psc1, *psh1, *psc2, *psh2, *pci, *pdj, *pws;
    cudaGetSymbolAddress(&pP, g_P);
    cudaGetSymbolAddress(&pQ, g_Q);
    cudaGetSymbolAddress(&pX1, g_X1);
    cudaGetSymbolAddress(&pX2, g_X2);
    cudaGetSymbolAddress(&phij, g_hij);
    cudaGetSymbolAddress(&pE, g_E);
    cudaGetSymbolAddress(&pS, g_S);
    cudaGetSymbolAddress(&psc1, g_sc1);
    cudaGetSymbolAddress(&psh1, g_sh1);
    cudaGetSymbolAddress(&psc2, g_sc2);
    cudaGetSymbolAddress(&psh2, g_sh2);
    cudaGetSymbolAddress(&pci, g_ci);
    cudaGetSymbolAddress(&pdj, g_dj);
    cudaGetSymbolAddress(&pws, g_ws);

    float* P = (float*)pP;
    float* Q = (float*)pQ;
    float* X1 = (float*)pX1;
    float* X2 = (float*)pX2;
    float* hij = (float*)phij;
    float* E = (float*)pE;
    float* S = (float*)pS;
    float* sc1 = (float*)psc1;
    float* sh1 = (float*)psh1;
    float* sc2 = (float*)psc2;
    float* sh2 = (float*)psh2;
    float* ci = (float*)pci;
    float* dj = (float*)pdj;
    float* ws = (float*)pws;

    // 1) GEMM1: features @ W1, split-K8 -> P planes 0..7
    gemm_k<false, false, false><<<dim3(4, 32, 8), 128>>>(
        features, W1, P, 2048, 256, nullptr, nullptr, nullptr);
    // 2) X1 = sum(P)+b1; BN1 stats
    stats_phase1<8><<<256, 256>>>(P, b1, X1, S);
    stats_phase2<<<8, 256>>>(S, g1, bt1, sc1, sh1);
    // 3) GEMM2: relu(BN1(X1)) @ W2, split-K2 -> Q planes 0..1
    gemm_k<false, true, false><<<dim3(4, 32, 2), 128>>>(
        X1, W2, Q, 256, 128, nullptr, sc1, sh1);
    // 4) X2 = sum(Q)+b2; BN2 stats
    stats_phase1<2><<<256, 256>>>(Q, b2, X2, S);
    stats_phase2<<<8, 256>>>(S, g2, bt2, sc2, sh2);
    // 5) GEMM3: di @ We1 halves (di = relu(BN2(X2)) fused on A-load) -> hij
    gemm_k<true, true, false><<<dim3(4, 32, 2), 128>>>(
        X2, We1, hij, 256, 256, bwe1, sc2, sh2);
    // 6) ci/dj GEMVs
    cidj_kernel<<<256, 256>>>(hij, We2, ci, dj);
    // 7) edge weights
    edge_kernel<<<dim3(8, 32), 128>>>(hij, hij + (size_t)NN * H, We2, bwe2,
                                      labels, ci, dj, E);
    // 8) row sums
    row_sum<<<NN, 256>>>(E, ws);
    // 9) GEMM4: E @ di (di fused on B-load from X2), split-K8 -> P planes
    gemm_k<false, false, true><<<dim3(4, 32, 8), 128>>>(
        E, X2, P, 1024, 128, nullptr, sc2, sh2);
    // 10) out = di + sum(P)/wsum (di inline)
    reduce_epi<<<256, 256>>>(P, X2, sc2, sh2, ws, out);
}

// round 6
// speedup vs baseline: 1.0628x; 1.0628x over previous
#include <cuda_runtime.h>
#include <cuda_bf16.h>
#include <math.h>

#define NN 1024
#define H 256

typedef unsigned long long u64;

// ---------------- f32x2 packed helpers (sm_103a) ----------------------------
__device__ __forceinline__ u64 add2(u64 a, u64 b) {
    u64 r; asm("add.rn.f32x2 %0,%1,%2;" : "=l"(r) : "l"(a), "l"(b)); return r;
}
__device__ __forceinline__ void fma2(u64& d, u64 a, u64 b) {
    asm("fma.rn.f32x2 %0,%1,%2,%0;" : "+l"(d) : "l"(a), "l"(b));
}
__device__ __forceinline__ float2 unpack2(u64 v) {
    float2 r; asm("mov.b64 {%0,%1},%2;" : "=f"(r.x), "=f"(r.y) : "l"(v)); return r;
}

// ---------------- cp.async helpers ------------------------------------------
__device__ __forceinline__ void cp8(void* dst_smem, const void* src) {
    unsigned d = (unsigned)__cvta_generic_to_shared(dst_smem);
    asm volatile("cp.async.ca.shared.global [%0], [%1], 8;" :: "r"(d), "l"(src));
}
__device__ __forceinline__ void cp_commit() {
    asm volatile("cp.async.commit_group;" ::: "memory");
}
template <int N>
__device__ __forceinline__ void cp_wait() {
    asm volatile("cp.async.wait_group %0;" :: "n"(N) : "memory");
}

// ---------------- scratch ----------------------------------------------------
__device__ float g_P[8 * NN * H];
__device__ float g_Q[4 * NN * H];
__device__ float g_X1[NN * H];
__device__ float g_X2[NN * H];
__device__ float g_hij[2 * NN * H];  // plane 0 = hi, plane 1 = hjb
__device__ float g_E[NN * NN];
__device__ float g_S[256 * 512];
__device__ float g_sc1[H], g_sh1[H];
__device__ float g_sc2[H], g_sh2[H];
__device__ float g_ci[NN], g_dj[NN];

// ---------------- GEMM: tile 32x64, 128 thr, f32x2 K-packed -----------------
// DUAL:  z>>1 selects B half (B + (z>>1)*H*H), z&1 selects K chunk (len KS).
// else:  z selects K chunk (len KS).
// Output always plane z: C0 + z*NN*H.
// BNA: A transformed on load: relu(fma(a, bnsc[k], bnsh[k]))   (k-indexed)
// BNB: B transformed on load: relu(fma(b, bnsc[col], bnsh[col])) (col-indexed)
template <bool DUAL, bool BNA, bool BNB>
__global__ __launch_bounds__(128) void gemm_k(
    const float* __restrict__ A, const float* __restrict__ B,
    float* __restrict__ C0, int K, int KS,
    const float* __restrict__ bnsc, const float* __restrict__ bnsh) {
    __shared__ float As[2][32][18];
    __shared__ float Bs[2][64][18];

    const int t = threadIdx.x;
    const int tx = t & 15;
    const int ty = t >> 4;
    const int I = blockIdx.y * 32;
    const int J = blockIdx.x * 64;
    const int z = blockIdx.z;

    const float* Bp = DUAL ? (B + (size_t)(z >> 1) * H * H) : B;
    const int kbase = (DUAL ? (z & 1) : z) * KS;
    float* Cp = C0 + (size_t)z * NN * H;

    float scvB = 0.f, shvB = 0.f;
    if (BNB) {
        const int col = J + (t & 63);
        scvB = bnsc[col];
        shvB = bnsh[col];
    }

    const int kiters = KS >> 4;
    float ra[4], rb[8];

    auto loadA = [&](int kt) {
        const int c = t & 15;
        const int kc = kbase + kt * 16 + c;
        float scv = 0.f, shv = 0.f;
        if (BNA) { scv = bnsc[kc]; shv = bnsh[kc]; }
#pragma unroll
        for (int e = 0; e < 4; e++) {
            int r = (t >> 4) + e * 8;
            float v = A[(size_t)(I + r) * K + kc];
            if (BNA) v = fmaxf(fmaf(v, scv, shv), 0.f);
            ra[e] = v;
        }
    };
    auto loadB = [&](int kt) {
        const int c = t & 63;
        const int r0 = t >> 6;
#pragma unroll
        for (int e = 0; e < 8; e++) {
            int r = r0 + e * 2;
            float v = Bp[(size_t)(kbase + kt * 16 + r) * H + J + c];
            if (BNB) v = fmaxf(fmaf(v, scvB, shvB), 0.f);
            rb[e] = v;
        }
    };
    auto stageS = [&](int buf) {
        const int ca = t & 15;
#pragma unroll
        for (int e = 0; e < 4; e++) As[buf][(t >> 4) + e * 8][ca] = ra[e];
        const int cb = t & 63;
        const int r0 = t >> 6;
#pragma unroll
        for (int e = 0; e < 8; e++) Bs[buf][cb][r0 + e * 2] = rb[e];
    };

    u64 acc[4][4];
#pragma unroll
    for (int m = 0; m < 4; m++)
#pragma unroll
        for (int n = 0; n < 4; n++) acc[m][n] = 0ull;

    loadA(0); loadB(0);
    stageS(0);
    __syncthreads();

    for (int kt = 0; kt < kiters; kt++) {
        const int buf = kt & 1;
        if (kt + 1 < kiters) { loadA(kt + 1); loadB(kt + 1); }
#pragma unroll
        for (int kp = 0; kp < 8; kp++) {
            u64 aP[4], bP[4];
#pragma unroll
            for (int m = 0; m < 4; m++)
                aP[m] = *(const u64*)&As[buf][ty * 4 + m][kp * 2];
#pragma unroll
            for (int n = 0; n < 4; n++)
                bP[n] = *(const u64*)&Bs[buf][tx + n * 16][kp * 2];
#pragma unroll
            for (int m = 0; m < 4; m++)
#pragma unroll
                for (int n = 0; n < 4; n++) fma2(acc[m][n], aP[m], bP[n]);
        }
        if (kt + 1 < kiters) {
            stageS(buf ^ 1);
            __syncthreads();
        }
    }

#pragma unroll
    for (int m = 0; m < 4; m++) {
        const int row = I + ty * 4 + m;
#pragma unroll
        for (int n = 0; n < 4; n++) {
            const int col = J + tx + n * 16;
            float2 p = unpack2(acc[m][n]);
            Cp[(size_t)row * H + col] = p.x + p.y;
        }
    }
}

// ---------------- BN stats phase1: X = sum(P)+bias, partial s/sq ------------
template <int NP>
__global__ void stats_phase1(const float* __restrict__ P, const float* __restrict__ bias,
                             float* __restrict__ X, float* __restrict__ S) {
    const int t = threadIdx.x;
    const int c4 = t & 63;
    const int rg = t >> 6;
    const int row = blockIdx.x * 4 + rg;
    float4 bv = ((const float4*)bias)[c4];
    constexpr size_t Q = NN * H / 4;
    size_t idx = (size_t)row * 64 + c4;
    float4 v = bv;
#pragma unroll
    for (int p = 0; p < NP; p++) {
        float4 a = ((const float4*)P)[(size_t)p * Q + idx];
        v.x += a.x; v.y += a.y; v.z += a.z; v.w += a.w;
    }
    ((float4*)X)[idx] = v;
    float4 q;
    q.x = v.x * v.x; q.y = v.y * v.y; q.z = v.z * v.z; q.w = v.w * v.w;
    __shared__ float4 sm[4][64], qm[4][64];
    sm[rg][c4] = v;
    qm[rg][c4] = q;
    __syncthreads();
    if (t < 64) {
        float4 S4 = make_float4(0.f, 0.f, 0.f, 0.f);
        float4 Q4 = make_float4(0.f, 0.f, 0.f, 0.f);
#pragma unroll
        for (int p = 0; p < 4; p++) {
            float4 a = sm[p][t], b = qm[p][t];
            S4.x += a.x; S4.y += a.y; S4.z += a.z; S4.w += a.w;
            Q4.x += b.x; Q4.y += b.y; Q4.z += b.z; Q4.w += b.w;
        }
        ((float4*)S)[blockIdx.x * 128 + t] = S4;
        ((float4*)S)[blockIdx.x * 128 + 64 + t] = Q4;
    }
}

// ---------------- BN stats phase2 -------------------------------------------
__global__ void stats_phase2(const float* __restrict__ S, const float* __restrict__ g,
                             const float* __restrict__ bt, float* __restrict__ sc,
                             float* __restrict__ sh) {
    const int t = threadIdx.x;
    const int c = blockIdx.x * 32 + (t & 31);
    const int pg = t >> 5;
    float s = 0.f, q = 0.f;
#pragma unroll
    for (int p = pg; p < 256; p += 8) {
        s += S[p * 512 + c];
        q += S[p * 512 + 256 + c];
    }
    __shared__ float sm[8][32], qm[8][32];
    sm[pg][t & 31] = s;
    qm[pg][t & 31] = q;
    __syncthreads();
    if (t < 32) {
        float S_ = 0.f, Q_ = 0.f;
#pragma unroll
        for (int p = 0; p < 8; p++) { S_ += sm[p][t]; Q_ += qm[p][t]; }
        const int col = blockIdx.x * 32 + t;
        float m = S_ * (1.f / NN);
        float var = Q_ * (1.f / NN) - m * m;
        float scv = g[col] * rsqrtf(var + 1e-5f);
        sc[col] = scv;
        sh[col] = bt[col] - m * scv;
    }
}

// ---------------- combine GEMM3 partials + ci/dj GEMVs ----------------------
// hi[r] = Q0[r]+Q1[r]; hjb[r] = Q2[r]+Q3[r]+bwe1; ci = 0.5*hi.We2; dj = 0.5*hjb.We2
__global__ void combine_cidj(const float* __restrict__ Q, const float* __restrict__ bwe1,
                             const float* __restrict__ We2,
                             float* __restrict__ hi, float* __restrict__ hjb,
                             float* __restrict__ ci, float* __restrict__ dj) {
    const int r = blockIdx.x;
    const int t = threadIdx.x;  // 0..255
    const bool isB = t >= 128;
    const int tt = t & 127;
    constexpr size_t PL = (size_t)NN * H;
    const float* P0 = Q + (isB ? 2 * PL : 0);
    const float* P1 = P0 + PL;
    float* dst = isB ? hjb : hi;
    float partial = 0.f;
#pragma unroll
    for (int e = 0; e < 2; e++) {
        const int c = tt + e * 128;
        float v = P0[(size_t)r * H + c] + P1[(size_t)r * H + c];
        if (isB) v += bwe1[c];
        dst[(size_t)r * H + c] = v;
        partial = fmaf(v, We2[c], partial);
    }
#pragma unroll
    for (int o = 16; o > 0; o >>= 1) partial += __shfl_xor_sync(~0u, partial, o);
    __shared__ float red[8];
    if ((t & 31) == 0) red[t >> 5] = partial;
    __syncthreads();
    if (t == 0) ci[r] = 0.5f * (red[0] + red[1] + red[2] + red[3]);
    if (t == 128) dj[r] = 0.5f * (red[4] + red[5] + red[6] + red[7]);
}

// ---------------- Edge kernel: 32x64 tile, swizzled cp.async ----------------
// logit = 0.5*sum_h w*|a+b| + ci[i] + dj[j] + bwe2
// smem: float2[row][16] per 32-h chunk; (r, c2) stored at column c2^(r&15).
// Read bank = 2*(hp^tx) -> conflict-free LDS.64.
__global__ __launch_bounds__(128) void edge_kernel(
    const float* __restrict__ hi, const float* __restrict__ hjb,
    const float* __restrict__ We2, const float* __restrict__ bwe2,
    const int* __restrict__ labels,
    const float* __restrict__ ci, const float* __restrict__ dj,
    float* __restrict__ E) {
    __shared__ float2 sa[2][32][16];
    __shared__ float2 sb[2][64][16];
    __shared__ float sw[256];
    __shared__ int li[32], lj[64];
    __shared__ float sci[32], sdj[64];

    const int t = threadIdx.x;
    const int tx = t & 15;
    const int ty = t >> 4;  // 0..7
    const int I = blockIdx.y * 32;
    const int J = blockIdx.x * 64;

    sw[t] = 0.5f * We2[t];
    sw[t + 128] = 0.5f * We2[t + 128];
    if (t < 32) { li[t] = labels[I + t]; sci[t] = ci[I + t]; }
    if (t < 64) { lj[t] = labels[J + t]; sdj[t] = dj[J + t]; }

    auto stage = [&](int c) {
        const int buf = c & 1;
        const int hoff = c * 32;
#pragma unroll
        for (int k = 0; k < 12; k++) {
            int p = t + k * 128;  // 0..1535
            if (p < 512) {
                int r = p >> 4, c2 = p & 15;
                cp8(&sa[buf][r][c2 ^ (r & 15)],
                    hi + (size_t)(I + r) * H + hoff + c2 * 2);
            } else {
                int q = p - 512;  // 0..1023
                int r = q >> 4, c2 = q & 15;
                cp8(&sb[buf][r][c2 ^ (r & 15)],
                    hjb + (size_t)(J + r) * H + hoff + c2 * 2);
            }
        }
    };

    u64 acc[4][4];
#pragma unroll
    for (int m = 0; m < 4; m++)
#pragma unroll
        for (int n = 0; n < 4; n++) acc[m][n] = 0ull;

    stage(0);
    cp_commit();

    for (int c = 0; c < 8; c++) {
        if (c < 7) {
            stage(c + 1);
            cp_commit();
            cp_wait<1>();
        } else {
            cp_wait<0>();
        }
        __syncthreads();
        const int buf = c & 1;
        const float* swc = &sw[c * 32];
#pragma unroll
        for (int hp = 0; hp < 16; hp++) {
            u64 w = *(const u64*)&swc[hp * 2];
            u64 aP[4], bP[4];
#pragma unroll
            for (int m = 0; m < 4; m++) {
                const int r = ty + m * 8;
                aP[m] = *(const u64*)&sa[buf][r][hp ^ (r & 15)];
            }
#pragma unroll
            for (int n = 0; n < 4; n++)
                bP[n] = *(const u64*)&sb[buf][tx + n * 16][hp ^ tx];
#pragma unroll
            for (int m = 0; m < 4; m++)
#pragma unroll
                for (int n = 0; n < 4; n++) {
                    u64 s = add2(aP[m], bP[n]) & 0x7FFFFFFF7FFFFFFFull;
                    fma2(acc[m][n], s, w);
                }
        }
        __syncthreads();
    }

    const float bw = bwe2[0];
#pragma unroll
    for (int m = 0; m < 4; m++) {
        const int il = ty + m * 8;
        const int i = I + il;
        const int la = li[il];
        const float cv = sci[il] + bw;
#pragma unroll
        for (int n = 0; n < 4; n++) {
            const int jl = tx + n * 16;
            const int j = J + jl;
            float2 p = unpack2(acc[m][n]);
            float logit = p.x + p.y + cv + sdj[jl];
            float e = (la == lj[jl] && i != j)
                          ? 1.f / (1.f + __expf(-logit)) : 0.f;
            E[(size_t)i * NN + j] = e;
        }
    }
}

// ---------------- final: wsum inline; out = di + sum(P)/wsum ----------------
// 256 blocks x 256 thr; block handles 4 rows. di recomputed from X2.
__global__ void reduce_epi(const float* __restrict__ P, const float* __restrict__ E,
                           const float* __restrict__ X2,
                           const float* __restrict__ sc, const float* __restrict__ sh,
                           float* __restrict__ out) {
    const int t = threadIdx.x;
    const int rg = t >> 6;   // row within block (0..3)
    const int c4 = t & 63;   // float4 col
    const int row = blockIdx.x * 4 + rg;

    // row sum of E[row][:]
    float s = 0.f;
    const float4* Er = (const float4*)(E + (size_t)row * NN);
#pragma unroll
    for (int e = 0; e < 4; e++) {
        float4 v = Er[c4 + e * 64];
        s += v.x + v.y + v.z + v.w;
    }
#pragma unroll
    for (int o = 16; o > 0; o >>= 1) s += __shfl_xor_sync(~0u, s, o);
    __shared__ float sm[8];
    if ((t & 31) == 0) sm[t >> 5] = s;
    __syncthreads();
    const float w = sm[rg * 2] + sm[rg * 2 + 1];
    const float inv = w > 0.f ? 1.f / w : 0.f;

    constexpr size_t Q = NN * H / 4;
    const size_t idx = (size_t)row * 64 + c4;
    float4 acc = make_float4(0.f, 0.f, 0.f, 0.f);
#pragma unroll
    for (int p = 0; p < 8; p++) {
        float4 a = ((const float4*)P)[p * Q + idx];
        acc.x += a.x; acc.y += a.y; acc.z += a.z; acc.w += a.w;
    }
    float4 x = ((const float4*)X2)[idx];
    float4 scv = ((const float4*)sc)[c4];
    float4 shv = ((const float4*)sh)[c4];
    float4 d;
    d.x = fmaxf(fmaf(x.x, scv.x, shv.x), 0.f);
    d.y = fmaxf(fmaf(x.y, scv.y, shv.y), 0.f);
    d.z = fmaxf(fmaf(x.z, scv.z, shv.z), 0.f);
    d.w = fmaxf(fmaf(x.w, scv.w, shv.w), 0.f);
    float4 o;
    o.x = fmaf(acc.x, inv, d.x);
    o.y = fmaf(acc.y, inv, d.y);
    o.z = fmaf(acc.z, inv, d.z);
    o.w = fmaf(acc.w, inv, d.w);
    ((float4*)out)[idx] = o;
}

// ---------------- launch -----------------------------------------------------
extern "C" void kernel_launch(void* const* d_in, const int* in_sizes, int n_in,
                              void* d_out, int out_size) {
    const float* features = (const float*)d_in[0];
    const int* labels = (const int*)d_in[1];
    const float* W1 = (const float*)d_in[2];
    const float* b1 = (const float*)d_in[3];
    const float* g1 = (const float*)d_in[4];
    const float* bt1 = (const float*)d_in[5];
    const float* W2 = (const float*)d_in[6];
    const float* b2 = (const float*)d_in[7];
    const float* g2 = (const float*)d_in[8];
    const float* bt2 = (const float*)d_in[9];
    const float* We1 = (const float*)d_in[10];
    const float* bwe1 = (const float*)d_in[11];
    const float* We2 = (const float*)d_in[12];
    const float* bwe2 = (const float*)d_in[13];
    float* out = (float*)d_out;

    void *pP, *pQ, *pX1, *pX2, *phij, *pE, *pS, *psc1, *psh1, *psc2, *psh2, *pci, *pdj;
    cudaGetSymbolAddress(&pP, g_P);
    cudaGetSymbolAddress(&pQ, g_Q);
    cudaGetSymbolAddress(&pX1, g_X1);
    cudaGetSymbolAddress(&pX2, g_X2);
    cudaGetSymbolAddress(&phij, g_hij);
    cudaGetSymbolAddress(&pE, g_E);
    cudaGetSymbolAddress(&pS, g_S);
    cudaGetSymbolAddress(&psc1, g_sc1);
    cudaGetSymbolAddress(&psh1, g_sh1);
    cudaGetSymbolAddress(&psc2, g_sc2);
    cudaGetSymbolAddress(&psh2, g_sh2);
    cudaGetSymbolAddress(&pci, g_ci);
    cudaGetSymbolAddress(&pdj, g_dj);

    float* P = (float*)pP;
    float* Q = (float*)pQ;
    float* X1 = (float*)pX1;
    float* X2 = (float*)pX2;
    float* hij = (float*)phij;
    float* E = (float*)pE;
    float* S = (float*)pS;
    float* sc1 = (float*)psc1;
    float* sh1 = (float*)psh1;
    float* sc2 = (float*)psc2;
    float* sh2 = (float*)psh2;
    float* ci = (float*)pci;
    float* dj = (float*)pdj;

    // 1) GEMM1: features @ W1, split-K8 -> P planes 0..7   (1024 blocks)
    gemm_k<false, false, false><<<dim3(4, 32, 8), 128>>>(
        features, W1, P, 2048, 256, nullptr, nullptr);
    // 2) X1 = sum(P)+b1; BN1 stats
    stats_phase1<8><<<256, 256>>>(P, b1, X1, S);
    stats_phase2<<<8, 256>>>(S, g1, bt1, sc1, sh1);
    // 3) GEMM2: relu(BN1(X1)) @ W2 (BNA), split-K4 -> Q planes 0..3  (512 blocks)
    gemm_k<false, true, false><<<dim3(4, 32, 4), 128>>>(
        X1, W2, Q, 256, 64, sc1, sh1);
    // 4) X2 = sum(Q)+b2; BN2 stats
    stats_phase1<4><<<256, 256>>>(Q, b2, X2, S);
    stats_phase2<<<8, 256>>>(S, g2, bt2, sc2, sh2);
    // 5) GEMM3: di @ We1 dual halves, split-K2 each (BNA on A) -> Q planes 0..3 (512 blocks)
    gemm_k<true, true, false><<<dim3(4, 32, 4), 128>>>(
        X2, We1, Q, 256, 128, sc2, sh2);
    // 6) combine partials -> hi, hjb (+bwe1); ci/dj GEMVs  (1024 blocks)
    combine_cidj<<<NN, 256>>>(Q, bwe1, We2, hij, hij + (size_t)NN * H, ci, dj);
    // 7) edge weights  (512 blocks)
    edge_kernel<<<dim3(16, 32), 128>>>(hij, hij + (size_t)NN * H, We2, bwe2,
                                       labels, ci, dj, E);
    // 8) GEMM4: E @ di (BNB recomputes di from X2), split-K8 -> P planes 0..7 (1024 blocks)
    gemm_k<false, false, true><<<dim3(4, 32, 8), 128>>>(
        E, X2, P, 1024, 128, sc2, sh2);
    // 9) out = di + sum(P)/wsum  (wsum inline from E)
    reduce_epi<<<256, 256>>>(P, E, X2, sc2, sh2, out);
}

// round 7
// speedup vs baseline: 1.2212x; 1.1491x over previous
#include <cuda_runtime.h>
#include <cuda_bf16.h>
#include <math.h>

#define NN 1024
#define H 256

typedef unsigned long long u64;

// ---------------- f32x2 packed helpers (sm_103a) ----------------------------
__device__ __forceinline__ u64 add2(u64 a, u64 b) {
    u64 r; asm("add.rn.f32x2 %0,%1,%2;" : "=l"(r) : "l"(a), "l"(b)); return r;
}
__device__ __forceinline__ void fma2(u64& d, u64 a, u64 b) {
    asm("fma.rn.f32x2 %0,%1,%2,%0;" : "+l"(d) : "l"(a), "l"(b));
}
__device__ __forceinline__ float2 unpack2(u64 v) {
    float2 r; asm("mov.b64 {%0,%1},%2;" : "=f"(r.x), "=f"(r.y) : "l"(v)); return r;
}

// ---------------- cp.async helpers ------------------------------------------
__device__ __forceinline__ void cp8(void* dst_smem, const void* src) {
    unsigned d = (unsigned)__cvta_generic_to_shared(dst_smem);
    asm volatile("cp.async.ca.shared.global [%0], [%1], 8;" :: "r"(d), "l"(src));
}
__device__ __forceinline__ void cp_commit() {
    asm volatile("cp.async.commit_group;" ::: "memory");
}
template <int N>
__device__ __forceinline__ void cp_wait() {
    asm volatile("cp.async.wait_group %0;" :: "n"(N) : "memory");
}

// ---------------- scratch ----------------------------------------------------
__device__ float g_P[8 * NN * H];
__device__ float g_Q[4 * NN * H];
__device__ float g_X1[NN * H];
__device__ float g_X2[NN * H];
__device__ float g_hij[2 * NN * H];  // permuted: plane0 = hi, plane1 = hjb
__device__ float g_diP[NN * H];      // permuted di
__device__ float g_E[NN * NN];       // permuted (block-diagonal)
__device__ float g_S[256 * 512];
__device__ float g_sc1[H], g_sh1[H];
__device__ float g_sc2[H], g_sh2[H];
__device__ float g_ci[NN], g_dj[NN]; // permuted
__device__ int g_pos[NN], g_perm[NN], g_lsort[NN], g_cls[17];
__device__ int g_tlist[1024];
__device__ int g_tcnt[1];

// ---------------- GEMM: tile 32x64, 128 thr, f32x2 K-packed (as R6) ---------
template <bool DUAL, bool BNA>
__global__ __launch_bounds__(128) void gemm_k(
    const float* __restrict__ A, const float* __restrict__ B,
    float* __restrict__ C0, int K, int KS,
    const float* __restrict__ bnsc, const float* __restrict__ bnsh) {
    __shared__ float As[2][32][18];
    __shared__ float Bs[2][64][18];

    const int t = threadIdx.x;
    const int tx = t & 15;
    const int ty = t >> 4;
    const int I = blockIdx.y * 32;
    const int J = blockIdx.x * 64;
    const int z = blockIdx.z;

    const float* Bp = DUAL ? (B + (size_t)(z >> 1) * H * H) : B;
    const int kbase = (DUAL ? (z & 1) : z) * KS;
    float* Cp = C0 + (size_t)z * NN * H;

    const int kiters = KS >> 4;
    float ra[4], rb[8];

    auto loadA = [&](int kt) {
        const int c = t & 15;
        const int kc = kbase + kt * 16 + c;
        float scv = 0.f, shv = 0.f;
        if (BNA) { scv = bnsc[kc]; shv = bnsh[kc]; }
#pragma unroll
        for (int e = 0; e < 4; e++) {
            int r = (t >> 4) + e * 8;
            float v = A[(size_t)(I + r) * K + kc];
            if (BNA) v = fmaxf(fmaf(v, scv, shv), 0.f);
            ra[e] = v;
        }
    };
    auto loadB = [&](int kt) {
        const int c = t & 63;
        const int r0 = t >> 6;
#pragma unroll
        for (int e = 0; e < 8; e++) {
            int r = r0 + e * 2;
            rb[e] = Bp[(size_t)(kbase + kt * 16 + r) * H + J + c];
        }
    };
    auto stageS = [&](int buf) {
        const int ca = t & 15;
#pragma unroll
        for (int e = 0; e < 4; e++) As[buf][(t >> 4) + e * 8][ca] = ra[e];
        const int cb = t & 63;
        const int r0 = t >> 6;
#pragma unroll
        for (int e = 0; e < 8; e++) Bs[buf][cb][r0 + e * 2] = rb[e];
    };

    u64 acc[4][4];
#pragma unroll
    for (int m = 0; m < 4; m++)
#pragma unroll
        for (int n = 0; n < 4; n++) acc[m][n] = 0ull;

    loadA(0); loadB(0);
    stageS(0);
    __syncthreads();

    for (int kt = 0; kt < kiters; kt++) {
        const int buf = kt & 1;
        if (kt + 1 < kiters) { loadA(kt + 1); loadB(kt + 1); }
#pragma unroll
        for (int kp = 0; kp < 8; kp++) {
            u64 aP[4], bP[4];
#pragma unroll
            for (int m = 0; m < 4; m++)
                aP[m] = *(const u64*)&As[buf][ty * 4 + m][kp * 2];
#pragma unroll
            for (int n = 0; n < 4; n++)
                bP[n] = *(const u64*)&Bs[buf][tx + n * 16][kp * 2];
#pragma unroll
            for (int m = 0; m < 4; m++)
#pragma unroll
                for (int n = 0; n < 4; n++) fma2(acc[m][n], aP[m], bP[n]);
        }
        if (kt + 1 < kiters) {
            stageS(buf ^ 1);
            __syncthreads();
        }
    }

#pragma unroll
    for (int m = 0; m < 4; m++) {
        const int row = I + ty * 4 + m;
#pragma unroll
        for (int n = 0; n < 4; n++) {
            const int col = J + tx + n * 16;
            float2 p = unpack2(acc[m][n]);
            Cp[(size_t)row * H + col] = p.x + p.y;
        }
    }
}

// ---------------- GEMM4: E(perm, block-diag) @ diP, dynamic k-range ---------
__global__ __launch_bounds__(128) void gemm4_range(
    const float* __restrict__ E, const float* __restrict__ diP,
    const int* __restrict__ lsort, const int* __restrict__ cls,
    float* __restrict__ C) {
    __shared__ float As[2][32][18];
    __shared__ float Bs[2][64][18];

    const int t = threadIdx.x;
    const int tx = t & 15;
    const int ty = t >> 4;
    const int I = blockIdx.y * 32;
    const int J = blockIdx.x * 64;

    const int lmin = lsort[I];
    const int lmax = lsort[I + 31];
    const int kmin = cls[lmin] & ~15;
    int kmax = (cls[lmax + 1] + 15) & ~15;
    if (kmax > NN) kmax = NN;
    const int kiters = (kmax - kmin) >> 4;

    float ra[4], rb[8];
    auto loadA = [&](int kt) {
        const int c = t & 15;
        const int kc = kmin + kt * 16 + c;
#pragma unroll
        for (int e = 0; e < 4; e++) {
            int r = (t >> 4) + e * 8;
            ra[e] = E[(size_t)(I + r) * NN + kc];
        }
    };
    auto loadB = [&](int kt) {
        const int c = t & 63;
        const int r0 = t >> 6;
#pragma unroll
        for (int e = 0; e < 8; e++) {
            int r = r0 + e * 2;
            rb[e] = diP[(size_t)(kmin + kt * 16 + r) * H + J + c];
        }
    };
    auto stageS = [&](int buf) {
        const int ca = t & 15;
#pragma unroll
        for (int e = 0; e < 4; e++) As[buf][(t >> 4) + e * 8][ca] = ra[e];
        const int cb = t & 63;
        const int r0 = t >> 6;
#pragma unroll
        for (int e = 0; e < 8; e++) Bs[buf][cb][r0 + e * 2] = rb[e];
    };

    u64 acc[4][4];
#pragma unroll
    for (int m = 0; m < 4; m++)
#pragma unroll
        for (int n = 0; n < 4; n++) acc[m][n] = 0ull;

    loadA(0); loadB(0);
    stageS(0);
    __syncthreads();

    for (int kt = 0; kt < kiters; kt++) {
        const int buf = kt & 1;
        if (kt + 1 < kiters) { loadA(kt + 1); loadB(kt + 1); }
#pragma unroll
        for (int kp = 0; kp < 8; kp++) {
            u64 aP[4], bP[4];
#pragma unroll
            for (int m = 0; m < 4; m++)
                aP[m] = *(const u64*)&As[buf][ty * 4 + m][kp * 2];
#pragma unroll
            for (int n = 0; n < 4; n++)
                bP[n] = *(const u64*)&Bs[buf][tx + n * 16][kp * 2];
#pragma unroll
            for (int m = 0; m < 4; m++)
#pragma unroll
                for (int n = 0; n < 4; n++) fma2(acc[m][n], aP[m], bP[n]);
        }
        if (kt + 1 < kiters) {
            stageS(buf ^ 1);
            __syncthreads();
        }
    }

#pragma unroll
    for (int m = 0; m < 4; m++) {
        const int row = I + ty * 4 + m;
#pragma unroll
        for (int n = 0; n < 4; n++) {
            const int col = J + tx + n * 16;
            float2 p = unpack2(acc[m][n]);
            C[(size_t)row * H + col] = p.x + p.y;
        }
    }
}

// ---------------- BN stats phase1 / phase2 (as R6) ---------------------------
template <int NP>
__global__ void stats_phase1(const float* __restrict__ P, const float* __restrict__ bias,
                             float* __restrict__ X, float* __restrict__ S) {
    const int t = threadIdx.x;
    const int c4 = t & 63;
    const int rg = t >> 6;
    const int row = blockIdx.x * 4 + rg;
    float4 bv = ((const float4*)bias)[c4];
    constexpr size_t Q = NN * H / 4;
    size_t idx = (size_t)row * 64 + c4;
    float4 v = bv;
#pragma unroll
    for (int p = 0; p < NP; p++) {
        float4 a = ((const float4*)P)[(size_t)p * Q + idx];
        v.x += a.x; v.y += a.y; v.z += a.z; v.w += a.w;
    }
    ((float4*)X)[idx] = v;
    float4 q;
    q.x = v.x * v.x; q.y = v.y * v.y; q.z = v.z * v.z; q.w = v.w * v.w;
    __shared__ float4 sm[4][64], qm[4][64];
    sm[rg][c4] = v;
    qm[rg][c4] = q;
    __syncthreads();
    if (t < 64) {
        float4 S4 = make_float4(0.f, 0.f, 0.f, 0.f);
        float4 Q4 = make_float4(0.f, 0.f, 0.f, 0.f);
#pragma unroll
        for (int p = 0; p < 4; p++) {
            float4 a = sm[p][t], b = qm[p][t];
            S4.x += a.x; S4.y += a.y; S4.z += a.z; S4.w += a.w;
            Q4.x += b.x; Q4.y += b.y; Q4.z += b.z; Q4.w += b.w;
        }
        ((float4*)S)[blockIdx.x * 128 + t] = S4;
        ((float4*)S)[blockIdx.x * 128 + 64 + t] = Q4;
    }
}

__global__ void stats_phase2(const float* __restrict__ S, const float* __restrict__ g,
                             const float* __restrict__ bt, float* __restrict__ sc,
                             float* __restrict__ sh) {
    const int t = threadIdx.x;
    const int c = blockIdx.x * 32 + (t & 31);
    const int pg = t >> 5;
    float s = 0.f, q = 0.f;
#pragma unroll
    for (int p = pg; p < 256; p += 8) {
        s += S[p * 512 + c];
        q += S[p * 512 + 256 + c];
    }
    __shared__ float sm[8][32], qm[8][32];
    sm[pg][t & 31] = s;
    qm[pg][t & 31] = q;
    __syncthreads();
    if (t < 32) {
        float S_ = 0.f, Q_ = 0.f;
#pragma unroll
        for (int p = 0; p < 8; p++) { S_ += sm[p][t]; Q_ += qm[p][t]; }
        const int col = blockIdx.x * 32 + t;
        float m = S_ * (1.f / NN);
        float var = Q_ * (1.f / NN) - m * m;
        float scv = g[col] * rsqrtf(var + 1e-5f);
        sc[col] = scv;
        sh[col] = bt[col] - m * scv;
    }
}

// ---------------- rank/sort kernel: deterministic counting rank -------------
// grid 8 x 128 thr. Also fills cls_off[0..16] and resets tile counter.
__global__ void rank_kernel(const int* __restrict__ labels, int* __restrict__ pos,
                            int* __restrict__ perm, int* __restrict__ lsort,
                            int* __restrict__ cls, int* __restrict__ tcnt) {
    __shared__ int sl[NN];
    const int t = threadIdx.x;
    const int node = blockIdx.x * 128 + t;
#pragma unroll
    for (int e = 0; e < NN / 128; e++) sl[t + e * 128] = labels[t + e * 128];
    __syncthreads();
    const int my = sl[node];
    int r = 0;
#pragma unroll 8
    for (int j = 0; j < NN; j++) {
        int l = sl[j];
        r += (l < my) || (l == my && j < node);
    }
    pos[node] = r;
    perm[r] = node;
    lsort[r] = my;
    if (blockIdx.x == 0) {
        if (t <= 16) {
            int c = 0;
#pragma unroll 8
            for (int j = 0; j < NN; j++) c += (sl[j] < t);
            cls[t] = c;
        }
        if (t == 17) tcnt[0] = 0;
    }
}

// ---------------- di_perm: diP[pos[r]] = relu(BN2(X2[r])) --------------------
__global__ void apply_relu_perm(const float* __restrict__ X, const float* __restrict__ sc,
                                const float* __restrict__ sh, const int* __restrict__ pos,
                                float* __restrict__ Y) {
    const int idx = blockIdx.x * 256 + threadIdx.x;
    const int row = idx >> 6;
    const int c4 = idx & 63;
    float4 v = ((const float4*)X)[idx];
    float4 s = ((const float4*)sc)[c4];
    float4 h = ((const float4*)sh)[c4];
    float4 y;
    y.x = fmaxf(fmaf(v.x, s.x, h.x), 0.f);
    y.y = fmaxf(fmaf(v.y, s.y, h.y), 0.f);
    y.z = fmaxf(fmaf(v.z, s.z, h.z), 0.f);
    y.w = fmaxf(fmaf(v.w, s.w, h.w), 0.f);
    ((float4*)Y)[(size_t)pos[row] * 64 + c4] = y;
}

// ---------------- combine GEMM3 partials + ci/dj (permuted writes) -----------
__global__ void combine_cidj(const float* __restrict__ Q, const float* __restrict__ bwe1,
                             const float* __restrict__ We2, const int* __restrict__ pos,
                             float* __restrict__ hi, float* __restrict__ hjb,
                             float* __restrict__ ci, float* __restrict__ dj) {
    const int r = blockIdx.x;
    const int pr = pos[r];
    const int t = threadIdx.x;
    const bool isB = t >= 128;
    const int tt = t & 127;
    constexpr size_t PL = (size_t)NN * H;
    const float* P0 = Q + (isB ? 2 * PL : 0);
    const float* P1 = P0 + PL;
    float* dst = isB ? hjb : hi;
    float partial = 0.f;
#pragma unroll
    for (int e = 0; e < 2; e++) {
        const int c = tt + e * 128;
        float v = P0[(size_t)r * H + c] + P1[(size_t)r * H + c];
        if (isB) v += bwe1[c];
        dst[(size_t)pr * H + c] = v;
        partial = fmaf(v, We2[c], partial);
    }
#pragma unroll
    for (int o = 16; o > 0; o >>= 1) partial += __shfl_xor_sync(~0u, partial, o);
    __shared__ float red[8];
    if ((t & 31) == 0) red[t >> 5] = partial;
    __syncthreads();
    if (t == 0) ci[pr] = 0.5f * (red[0] + red[1] + red[2] + red[3]);
    if (t == 128) dj[pr] = 0.5f * (red[4] + red[5] + red[6] + red[7]);
}

// ---------------- zero E ------------------------------------------------------
__global__ void zero_E(float* __restrict__ E) {
    const int idx = blockIdx.x * 256 + threadIdx.x;
    ((float4*)E)[idx] = make_float4(0.f, 0.f, 0.f, 0.f);
}

// ---------------- worklist of active 32x32 tiles -----------------------------
__global__ void build_worklist(const int* __restrict__ lsort, int* __restrict__ tlist,
                               int* __restrict__ tcnt) {
    const int t = threadIdx.x;  // 0..1023
    const int ti = t >> 5, tj = t & 31;
    const int I = ti * 32, J = tj * 32;
    bool act = (lsort[I] <= lsort[J + 31]) && (lsort[J] <= lsort[I + 31]);
    if (act) {
        int k = atomicAdd(tcnt, 1);
        tlist[k] = (ti << 16) | tj;
    }
}

// ---------------- sparse edge kernel: active 32x32 tiles only ---------------
__global__ __launch_bounds__(128) void edge_sparse(
    const float* __restrict__ hi, const float* __restrict__ hjb,
    const float* __restrict__ We2, const float* __restrict__ bwe2,
    const int* __restrict__ lsort,
    const float* __restrict__ ci, const float* __restrict__ dj,
    const int* __restrict__ tlist, const int* __restrict__ tcnt,
    float* __restrict__ E) {
    __shared__ float2 sa[2][32][16];
    __shared__ float2 sb[2][32][16];
    __shared__ float sw[256];

    const int t = threadIdx.x;
    const int tx = t & 15;
    const int ty = t >> 4;  // 0..7
    sw[t] = 0.5f * We2[t];
    sw[t + 128] = 0.5f * We2[t + 128];
    const int n = tcnt[0];
    const float bw = bwe2[0];

    for (int w = blockIdx.x; w < n; w += gridDim.x) {
        const int tile = tlist[w];
        const int I = (tile >> 16) * 32;
        const int J = (tile & 0xffff) * 32;

        auto stage = [&](int c) {
            const int buf = c & 1;
            const int hoff = c * 32;
#pragma unroll
            for (int k = 0; k < 8; k++) {
                int p = t + k * 128;
                if (p < 512) {
                    int r = p >> 4, c2 = p & 15;
                    cp8(&sa[buf][r][c2 ^ (r & 15)],
                        hi + (size_t)(I + r) * H + hoff + c2 * 2);
                } else {
                    int q = p - 512;
                    int r = q >> 4, c2 = q & 15;
                    cp8(&sb[buf][r][c2 ^ (r & 15)],
                        hjb + (size_t)(J + r) * H + hoff + c2 * 2);
                }
            }
        };

        u64 acc[4][2];
#pragma unroll
        for (int m = 0; m < 4; m++)
#pragma unroll
            for (int nn2 = 0; nn2 < 2; nn2++) acc[m][nn2] = 0ull;

        stage(0);
        cp_commit();

        for (int c = 0; c < 8; c++) {
            if (c < 7) {
                stage(c + 1);
                cp_commit();
                cp_wait<1>();
            } else {
                cp_wait<0>();
            }
            __syncthreads();
            const int buf = c & 1;
            const float* swc = &sw[c * 32];
#pragma unroll
            for (int hp = 0; hp < 16; hp++) {
                u64 wv = *(const u64*)&swc[hp * 2];
                u64 aP[4], bP[2];
#pragma unroll
                for (int m = 0; m < 4; m++) {
                    const int r = ty + m * 8;
                    aP[m] = *(const u64*)&sa[buf][r][hp ^ (r & 15)];
                }
#pragma unroll
                for (int nn2 = 0; nn2 < 2; nn2++) {
                    const int r = tx + nn2 * 16;
                    bP[nn2] = *(const u64*)&sb[buf][r][hp ^ (r & 15)];
                }
#pragma unroll
                for (int m = 0; m < 4; m++)
#pragma unroll
                    for (int nn2 = 0; nn2 < 2; nn2++) {
                        u64 s = add2(aP[m], bP[nn2]) & 0x7FFFFFFF7FFFFFFFull;
                        fma2(acc[m][nn2], s, wv);
                    }
            }
            __syncthreads();
        }

#pragma unroll
        for (int m = 0; m < 4; m++) {
            const int i = I + ty + m * 8;
            const int la = lsort[i];
            const float cv = ci[i] + bw;
#pragma unroll
            for (int nn2 = 0; nn2 < 2; nn2++) {
                const int j = J + tx + nn2 * 16;
                float2 p = unpack2(acc[m][nn2]);
                float logit = p.x + p.y + cv + dj[j];
                float e = (la == lsort[j] && i != j)
                              ? 1.f / (1.f + __expf(-logit)) : 0.f;
                E[(size_t)i * NN + j] = e;
            }
        }
    }
}

// ---------------- final: wsum inline; out[perm[p]] = diP[p] + R[p]/wsum -----
__global__ void reduce_final(const float* __restrict__ P, const float* __restrict__ E,
                             const float* __restrict__ diP, const int* __restrict__ perm,
                             float* __restrict__ out) {
    const int t = threadIdx.x;
    const int rg = t >> 6;
    const int c4 = t & 63;
    const int p = blockIdx.x * 4 + rg;

    float s = 0.f;
    const float4* Er = (const float4*)(E + (size_t)p * NN);
#pragma unroll
    for (int e = 0; e < 4; e++) {
        float4 v = Er[c4 + e * 64];
        s += v.x + v.y + v.z + v.w;
    }
#pragma unroll
    for (int o = 16; o > 0; o >>= 1) s += __shfl_xor_sync(~0u, s, o);
    __shared__ float sm[8];
    if ((t & 31) == 0) sm[t >> 5] = s;
    __syncthreads();
    const float w = sm[rg * 2] + sm[rg * 2 + 1];
    const float inv = w > 0.f ? 1.f / w : 0.f;

    const size_t idx = (size_t)p * 64 + c4;
    float4 a = ((const float4*)P)[idx];
    float4 d = ((const float4*)diP)[idx];
    float4 o;
    o.x = fmaf(a.x, inv, d.x);
    o.y = fmaf(a.y, inv, d.y);
    o.z = fmaf(a.z, inv, d.z);
    o.w = fmaf(a.w, inv, d.w);
    ((float4*)out)[(size_t)perm[p] * 64 + c4] = o;
}

// ---------------- launch -----------------------------------------------------
extern "C" void kernel_launch(void* const* d_in, const int* in_sizes, int n_in,
                              void* d_out, int out_size) {
    const float* features = (const float*)d_in[0];
    const int* labels = (const int*)d_in[1];
    const float* W1 = (const float*)d_in[2];
    const float* b1 = (const float*)d_in[3];
    const float* g1 = (const float*)d_in[4];
    const float* bt1 = (const float*)d_in[5];
    const float* W2 = (const float*)d_in[6];
    const float* b2 = (const float*)d_in[7];
    const float* g2 = (const float*)d_in[8];
    const float* bt2 = (const float*)d_in[9];
    const float* We1 = (const float*)d_in[10];
    const float* bwe1 = (const float*)d_in[11];
    const float* We2 = (const float*)d_in[12];
    const float* bwe2 = (const float*)d_in[13];
    float* out = (float*)d_out;

    void *pP, *pQ, *pX1, *pX2, *phij, *pdiP, *pE, *pS;
    void *psc1, *psh1, *psc2, *psh2, *pci, *pdj;
    void *ppos, *pperm, *plsort, *pcls, *ptlist, *ptcnt;
    cudaGetSymbolAddress(&pP, g_P);
    cudaGetSymbolAddress(&pQ, g_Q);
    cudaGetSymbolAddress(&pX1, g_X1);
    cudaGetSymbolAddress(&pX2, g_X2);
    cudaGetSymbolAddress(&phij, g_hij);
    cudaGetSymbolAddress(&pdiP, g_diP);
    cudaGetSymbolAddress(&pE, g_E);
    cudaGetSymbolAddress(&pS, g_S);
    cudaGetSymbolAddress(&psc1, g_sc1);
    cudaGetSymbolAddress(&psh1, g_sh1);
    cudaGetSymbolAddress(&psc2, g_sc2);
    cudaGetSymbolAddress(&psh2, g_sh2);
    cudaGetSymbolAddress(&pci, g_ci);
    cudaGetSymbolAddress(&pdj, g_dj);
    cudaGetSymbolAddress(&ppos, g_pos);
    cudaGetSymbolAddress(&pperm, g_perm);
    cudaGetSymbolAddress(&plsort, g_lsort);
    cudaGetSymbolAddress(&pcls, g_cls);
    cudaGetSymbolAddress(&ptlist, g_tlist);
    cudaGetSymbolAddress(&ptcnt, g_tcnt);

    float* P = (float*)pP;
    float* Q = (float*)pQ;
    float* X1 = (float*)pX1;
    float* X2 = (float*)pX2;
    float* hij = (float*)phij;
    float* diP = (float*)pdiP;
    float* E = (float*)pE;
    float* S = (float*)pS;
    float* sc1 = (float*)psc1;
    float* sh1 = (float*)psh1;
    float* sc2 = (float*)psc2;
    float* sh2 = (float*)psh2;
    float* ci = (float*)pci;
    float* dj = (float*)pdj;
    int* pos = (int*)ppos;
    int* perm = (int*)pperm;
    int* lsort = (int*)plsort;
    int* cls = (int*)pcls;
    int* tlist = (int*)ptlist;
    int* tcnt = (int*)ptcnt;

    // 0) label ranking / permutation (also resets tile counter)
    rank_kernel<<<8, 128>>>(labels, pos, perm, lsort, cls, tcnt);
    // 0b) zero E (block-diagonal writes come later)
    zero_E<<<1024, 256>>>(E);
    // 0c) active tile worklist
    build_worklist<<<1, 1024>>>(lsort, tlist, tcnt);

    // 1) GEMM1: features @ W1, split-K8 -> P planes 0..7
    gemm_k<false, false><<<dim3(4, 32, 8), 128>>>(
        features, W1, P, 2048, 256, nullptr, nullptr);
    // 2) X1 = sum(P)+b1; BN1 stats
    stats_phase1<8><<<256, 256>>>(P, b1, X1, S);
    stats_phase2<<<8, 256>>>(S, g1, bt1, sc1, sh1);
    // 3) GEMM2: relu(BN1(X1)) @ W2 (BNA), split-K4 -> Q planes 0..3
    gemm_k<false, true><<<dim3(4, 32, 4), 128>>>(
        X1, W2, Q, 256, 64, sc1, sh1);
    // 4) X2 = sum(Q)+b2; BN2 stats
    stats_phase1<4><<<256, 256>>>(Q, b2, X2, S);
    stats_phase2<<<8, 256>>>(S, g2, bt2, sc2, sh2);
    // 5) diP[pos[r]] = relu(BN2(X2[r]))
    apply_relu_perm<<<256, 256>>>(X2, sc2, sh2, pos, diP);
    // 6) GEMM3: di @ We1 dual halves (BNA from X2), split-K2 -> Q planes 0..3
    gemm_k<true, true><<<dim3(4, 32, 4), 128>>>(
        X2, We1, Q, 256, 128, sc2, sh2);
    // 7) combine -> hi/hjb permuted (+bwe1), ci/dj permuted
    combine_cidj<<<NN, 256>>>(Q, bwe1, We2, pos, hij, hij + (size_t)NN * H, ci, dj);
    // 8) sparse edge weights (active tiles only)
    edge_sparse<<<296, 128>>>(hij, hij + (size_t)NN * H, We2, bwe2, lsort,
                              ci, dj, tlist, tcnt, E);
    // 9) GEMM4: E @ diP over per-tile class k-range -> P plane 0
    gemm4_range<<<dim3(4, 32), 128>>>(E, diP, lsort, cls, P);
    // 10) out[perm[p]] = diP[p] + R[p]/wsum[p]
    reduce_final<<<256, 256>>>(P, E, diP, perm, out);
}

// round 8
// speedup vs baseline: 1.2620x; 1.0335x over previous
#include <cuda_runtime.h>
#include <cuda_bf16.h>
#include <math.h>

#define NN 1024
#define H 256

typedef unsigned long long u64;

// ---------------- f32x2 packed helpers (sm_103a) ----------------------------
__device__ __forceinline__ u64 add2(u64 a, u64 b) {
    u64 r; asm("add.rn.f32x2 %0,%1,%2;" : "=l"(r) : "l"(a), "l"(b)); return r;
}
__device__ __forceinline__ void fma2(u64& d, u64 a, u64 b) {
    asm("fma.rn.f32x2 %0,%1,%2,%0;" : "+l"(d) : "l"(a), "l"(b));
}
__device__ __forceinline__ float2 unpack2(u64 v) {
    float2 r; asm("mov.b64 {%0,%1},%2;" : "=f"(r.x), "=f"(r.y) : "l"(v)); return r;
}

// ---------------- cp.async helpers ------------------------------------------
__device__ __forceinline__ void cp8(void* dst_smem, const void* src) {
    unsigned d = (unsigned)__cvta_generic_to_shared(dst_smem);
    asm volatile("cp.async.ca.shared.global [%0], [%1], 8;" :: "r"(d), "l"(src));
}
__device__ __forceinline__ void cp_commit() {
    asm volatile("cp.async.commit_group;" ::: "memory");
}
template <int N>
__device__ __forceinline__ void cp_wait() {
    asm volatile("cp.async.wait_group %0;" :: "n"(N) : "memory");
}

// ---------------- scratch ----------------------------------------------------
__device__ float g_P[8 * NN * H];
__device__ float g_Q[4 * NN * H];
__device__ float g_X1[NN * H];
__device__ float g_X2[NN * H];
__device__ float g_hij[2 * NN * H];  // permuted: plane0 = hi, plane1 = hjb
__device__ float g_diP[NN * H];      // permuted di
__device__ float g_E[NN * NN];       // permuted (block-diagonal)
__device__ float g_S[256 * 512];
__device__ float g_sc1[H], g_sh1[H];
__device__ float g_sc2[H], g_sh2[H];
__device__ float g_ci[NN], g_dj[NN]; // permuted
__device__ int g_pos[NN], g_perm[NN], g_lsort[NN], g_cls[17];
__device__ int g_tlist[1024];
__device__ int g_tcnt[1];

// ---------------- GEMM: tile 32x64, 128 thr, LDS.128 operands ---------------
// DUAL:  z>>1 selects B half (B + (z>>1)*H*H), z&1 selects K chunk (len KS).
// else:  z selects K chunk (len KS).
// Output plane z: C0 + z*NN*H.
// BNA: A transformed on load: relu(fma(a, bnsc[k], bnsh[k]))  (k-indexed)
template <bool DUAL, bool BNA>
__global__ __launch_bounds__(128) void gemm_k(
    const float* __restrict__ A, const float* __restrict__ B,
    float* __restrict__ C0, int K, int KS,
    const float* __restrict__ bnsc, const float* __restrict__ bnsh) {
    __shared__ float As[2][32][20];   // [m][k], stride 20 (.128-aligned rows)
    __shared__ float Bs[2][64][20];   // [n][k]

    const int t = threadIdx.x;
    const int tx = t & 15;
    const int ty = t >> 4;
    const int I = blockIdx.y * 32;
    const int J = blockIdx.x * 64;
    const int z = blockIdx.z;

    const float* Bp = DUAL ? (B + (size_t)(z >> 1) * H * H) : B;
    const int kbase = (DUAL ? (z & 1) : z) * KS;
    float* Cp = C0 + (size_t)z * NN * H;

    const int kiters = KS >> 4;

    // staging registers
    float4 fa;
    float fb[8];
    const int ar = t >> 2, ac4 = t & 3;          // A: row, k-group
    const int bc = t & 63, bkh = (t >> 6) * 8;   // B: col, k-half

    auto loadA = [&](int kt) {
        const int kc = kbase + kt * 16 + ac4 * 4;
        fa = *(const float4*)&A[(size_t)(I + ar) * K + kc];
        if (BNA) {
            float4 s = *(const float4*)&bnsc[kc];
            float4 h = *(const float4*)&bnsh[kc];
            fa.x = fmaxf(fmaf(fa.x, s.x, h.x), 0.f);
            fa.y = fmaxf(fmaf(fa.y, s.y, h.y), 0.f);
            fa.z = fmaxf(fmaf(fa.z, s.z, h.z), 0.f);
            fa.w = fmaxf(fmaf(fa.w, s.w, h.w), 0.f);
        }
    };
    auto loadB = [&](int kt) {
        const int k0 = kbase + kt * 16 + bkh;
#pragma unroll
        for (int e = 0; e < 8; e++)
            fb[e] = Bp[(size_t)(k0 + e) * H + J + bc];
    };
    auto stageS = [&](int buf) {
        *(float4*)&As[buf][ar][ac4 * 4] = fa;
        *(float4*)&Bs[buf][bc][bkh] = make_float4(fb[0], fb[1], fb[2], fb[3]);
        *(float4*)&Bs[buf][bc][bkh + 4] = make_float4(fb[4], fb[5], fb[6], fb[7]);
    };

    u64 acc[4][4];
#pragma unroll
    for (int m = 0; m < 4; m++)
#pragma unroll
        for (int n = 0; n < 4; n++) acc[m][n] = 0ull;

    loadA(0); loadB(0);
    stageS(0);
    __syncthreads();

    for (int kt = 0; kt < kiters; kt++) {
        const int buf = kt & 1;
        if (kt + 1 < kiters) { loadA(kt + 1); loadB(kt + 1); }
#pragma unroll
        for (int g = 0; g < 4; g++) {   // 4 k-values per group
            float4 av[4], bv[4];
#pragma unroll
            for (int m = 0; m < 4; m++)
                av[m] = *(const float4*)&As[buf][ty * 4 + m][g * 4];
#pragma unroll
            for (int n = 0; n < 4; n++)
                bv[n] = *(const float4*)&Bs[buf][tx + n * 16][g * 4];
#pragma unroll
            for (int m = 0; m < 4; m++) {
                const u64 a01 = *(const u64*)&av[m].x;
                const u64 a23 = *(const u64*)&av[m].z;
#pragma unroll
                for (int n = 0; n < 4; n++) {
                    fma2(acc[m][n], a01, *(const u64*)&bv[n].x);
                    fma2(acc[m][n], a23, *(const u64*)&bv[n].z);
                }
            }
        }
        if (kt + 1 < kiters) {
            stageS(buf ^ 1);
            __syncthreads();
        }
    }

#pragma unroll
    for (int m = 0; m < 4; m++) {
        const int row = I + ty * 4 + m;
#pragma unroll
        for (int n = 0; n < 4; n++) {
            const int col = J + tx + n * 16;
            float2 p = unpack2(acc[m][n]);
            Cp[(size_t)row * H + col] = p.x + p.y;
        }
    }
}

// ---------------- GEMM4: E(perm, block-diag) @ diP, dynamic k-range ---------
__global__ __launch_bounds__(128) void gemm4_range(
    const float* __restrict__ E, const float* __restrict__ diP,
    const int* __restrict__ lsort, const int* __restrict__ cls,
    float* __restrict__ C) {
    __shared__ float As[2][32][20];
    __shared__ float Bs[2][64][20];

    const int t = threadIdx.x;
    const int tx = t & 15;
    const int ty = t >> 4;
    const int I = blockIdx.y * 32;
    const int J = blockIdx.x * 64;

    const int lmin = lsort[I];
    const int lmax = lsort[I + 31];
    const int kmin = cls[lmin] & ~15;
    int kmax = (cls[lmax + 1] + 15) & ~15;
    if (kmax > NN) kmax = NN;
    const int kiters = (kmax - kmin) >> 4;

    float4 fa;
    float fb[8];
    const int ar = t >> 2, ac4 = t & 3;
    const int bc = t & 63, bkh = (t >> 6) * 8;

    auto loadA = [&](int kt) {
        const int kc = kmin + kt * 16 + ac4 * 4;
        fa = *(const float4*)&E[(size_t)(I + ar) * NN + kc];
    };
    auto loadB = [&](int kt) {
        const int k0 = kmin + kt * 16 + bkh;
#pragma unroll
        for (int e = 0; e < 8; e++)
            fb[e] = diP[(size_t)(k0 + e) * H + J + bc];
    };
    auto stageS = [&](int buf) {
        *(float4*)&As[buf][ar][ac4 * 4] = fa;
        *(float4*)&Bs[buf][bc][bkh] = make_float4(fb[0], fb[1], fb[2], fb[3]);
        *(float4*)&Bs[buf][bc][bkh + 4] = make_float4(fb[4], fb[5], fb[6], fb[7]);
    };

    u64 acc[4][4];
#pragma unroll
    for (int m = 0; m < 4; m++)
#pragma unroll
        for (int n = 0; n < 4; n++) acc[m][n] = 0ull;

    loadA(0); loadB(0);
    stageS(0);
    __syncthreads();

    for (int kt = 0; kt < kiters; kt++) {
        const int buf = kt & 1;
        if (kt + 1 < kiters) { loadA(kt + 1); loadB(kt + 1); }
#pragma unroll
        for (int g = 0; g < 4; g++) {
            float4 av[4], bv[4];
#pragma unroll
            for (int m = 0; m < 4; m++)
                av[m] = *(const float4*)&As[buf][ty * 4 + m][g * 4];
#pragma unroll
            for (int n = 0; n < 4; n++)
                bv[n] = *(const float4*)&Bs[buf][tx + n * 16][g * 4];
#pragma unroll
            for (int m = 0; m < 4; m++) {
                const u64 a01 = *(const u64*)&av[m].x;
                const u64 a23 = *(const u64*)&av[m].z;
#pragma unroll
                for (int n = 0; n < 4; n++) {
                    fma2(acc[m][n], a01, *(const u64*)&bv[n].x);
                    fma2(acc[m][n], a23, *(const u64*)&bv[n].z);
                }
            }
        }
        if (kt + 1 < kiters) {
            stageS(buf ^ 1);
            __syncthreads();
        }
    }

#pragma unroll
    for (int m = 0; m < 4; m++) {
        const int row = I + ty * 4 + m;
#pragma unroll
        for (int n = 0; n < 4; n++) {
            const int col = J + tx + n * 16;
            float2 p = unpack2(acc[m][n]);
            C[(size_t)row * H + col] = p.x + p.y;
        }
    }
}

// ---------------- BN stats phase1 / phase2 -----------------------------------
template <int NP>
__global__ void stats_phase1(const float* __restrict__ P, const float* __restrict__ bias,
                             float* __restrict__ X, float* __restrict__ S) {
    const int t = threadIdx.x;
    const int c4 = t & 63;
    const int rg = t >> 6;
    const int row = blockIdx.x * 4 + rg;
    float4 bv = ((const float4*)bias)[c4];
    constexpr size_t Q = NN * H / 4;
    size_t idx = (size_t)row * 64 + c4;
    float4 v = bv;
#pragma unroll
    for (int p = 0; p < NP; p++) {
        float4 a = ((const float4*)P)[(size_t)p * Q + idx];
        v.x += a.x; v.y += a.y; v.z += a.z; v.w += a.w;
    }
    ((float4*)X)[idx] = v;
    float4 q;
    q.x = v.x * v.x; q.y = v.y * v.y; q.z = v.z * v.z; q.w = v.w * v.w;
    __shared__ float4 sm[4][64], qm[4][64];
    sm[rg][c4] = v;
    qm[rg][c4] = q;
    __syncthreads();
    if (t < 64) {
        float4 S4 = make_float4(0.f, 0.f, 0.f, 0.f);
        float4 Q4 = make_float4(0.f, 0.f, 0.f, 0.f);
#pragma unroll
        for (int p = 0; p < 4; p++) {
            float4 a = sm[p][t], b = qm[p][t];
            S4.x += a.x; S4.y += a.y; S4.z += a.z; S4.w += a.w;
            Q4.x += b.x; Q4.y += b.y; Q4.z += b.z; Q4.w += b.w;
        }
        ((float4*)S)[blockIdx.x * 128 + t] = S4;
        ((float4*)S)[blockIdx.x * 128 + 64 + t] = Q4;
    }
}

__global__ void stats_phase2(const float* __restrict__ S, const float* __restrict__ g,
                             const float* __restrict__ bt, float* __restrict__ sc,
                             float* __restrict__ sh) {
    const int t = threadIdx.x;
    const int c = blockIdx.x * 32 + (t & 31);
    const int pg = t >> 5;
    float s = 0.f, q = 0.f;
#pragma unroll
    for (int p = pg; p < 256; p += 8) {
        s += S[p * 512 + c];
        q += S[p * 512 + 256 + c];
    }
    __shared__ float sm[8][32], qm[8][32];
    sm[pg][t & 31] = s;
    qm[pg][t & 31] = q;
    __syncthreads();
    if (t < 32) {
        float S_ = 0.f, Q_ = 0.f;
#pragma unroll
        for (int p = 0; p < 8; p++) { S_ += sm[p][t]; Q_ += qm[p][t]; }
        const int col = blockIdx.x * 32 + t;
        float m = S_ * (1.f / NN);
        float var = Q_ * (1.f / NN) - m * m;
        float scv = g[col] * rsqrtf(var + 1e-5f);
        sc[col] = scv;
        sh[col] = bt[col] - m * scv;
    }
}

// ---------------- rank/sort kernel -------------------------------------------
__global__ void rank_kernel(const int* __restrict__ labels, int* __restrict__ pos,
                            int* __restrict__ perm, int* __restrict__ lsort,
                            int* __restrict__ cls, int* __restrict__ tcnt) {
    __shared__ int sl[NN];
    const int t = threadIdx.x;
    const int node = blockIdx.x * 128 + t;
#pragma unroll
    for (int e = 0; e < NN / 128; e++) sl[t + e * 128] = labels[t + e * 128];
    __syncthreads();
    const int my = sl[node];
    int r = 0;
#pragma unroll 8
    for (int j = 0; j < NN; j++) {
        int l = sl[j];
        r += (l < my) || (l == my && j < node);
    }
    pos[node] = r;
    perm[r] = node;
    lsort[r] = my;
    if (blockIdx.x == 0) {
        if (t <= 16) {
            int c = 0;
#pragma unroll 8
            for (int j = 0; j < NN; j++) c += (sl[j] < t);
            cls[t] = c;
        }
        if (t == 17) tcnt[0] = 0;
    }
}

// ---------------- diP[pos[r]] = relu(BN2(X2[r])) -----------------------------
__global__ void apply_relu_perm(const float* __restrict__ X, const float* __restrict__ sc,
                                const float* __restrict__ sh, const int* __restrict__ pos,
                                float* __restrict__ Y) {
    const int idx = blockIdx.x * 256 + threadIdx.x;
    const int row = idx >> 6;
    const int c4 = idx & 63;
    float4 v = ((const float4*)X)[idx];
    float4 s = ((const float4*)sc)[c4];
    float4 h = ((const float4*)sh)[c4];
    float4 y;
    y.x = fmaxf(fmaf(v.x, s.x, h.x), 0.f);
    y.y = fmaxf(fmaf(v.y, s.y, h.y), 0.f);
    y.z = fmaxf(fmaf(v.z, s.z, h.z), 0.f);
    y.w = fmaxf(fmaf(v.w, s.w, h.w), 0.f);
    ((float4*)Y)[(size_t)pos[row] * 64 + c4] = y;
}

// ---------------- combine GEMM3 partials + ci/dj (permuted writes) -----------
__global__ void combine_cidj(const float* __restrict__ Q, const float* __restrict__ bwe1,
                             const float* __restrict__ We2, const int* __restrict__ pos,
                             float* __restrict__ hi, float* __restrict__ hjb,
                             float* __restrict__ ci, float* __restrict__ dj) {
    const int r = blockIdx.x;
    const int pr = pos[r];
    const int t = threadIdx.x;
    const bool isB = t >= 128;
    const int tt = t & 127;
    constexpr size_t PL = (size_t)NN * H;
    const float* P0 = Q + (isB ? 2 * PL : 0);
    const float* P1 = P0 + PL;
    float* dst = isB ? hjb : hi;
    float partial = 0.f;
#pragma unroll
    for (int e = 0; e < 2; e++) {
        const int c = tt + e * 128;
        float v = P0[(size_t)r * H + c] + P1[(size_t)r * H + c];
        if (isB) v += bwe1[c];
        dst[(size_t)pr * H + c] = v;
        partial = fmaf(v, We2[c], partial);
    }
#pragma unroll
    for (int o = 16; o > 0; o >>= 1) partial += __shfl_xor_sync(~0u, partial, o);
    __shared__ float red[8];
    if ((t & 31) == 0) red[t >> 5] = partial;
    __syncthreads();
    if (t == 0) ci[pr] = 0.5f * (red[0] + red[1] + red[2] + red[3]);
    if (t == 128) dj[pr] = 0.5f * (red[4] + red[5] + red[6] + red[7]);
}

// ---------------- zero E ------------------------------------------------------
__global__ void zero_E(float* __restrict__ E) {
    const int idx = blockIdx.x * 256 + threadIdx.x;
    ((float4*)E)[idx] = make_float4(0.f, 0.f, 0.f, 0.f);
}

// ---------------- worklist of active 32x32 tiles -----------------------------
__global__ void build_worklist(const int* __restrict__ lsort, int* __restrict__ tlist,
                               int* __restrict__ tcnt) {
    const int t = threadIdx.x;
    const int ti = t >> 5, tj = t & 31;
    const int I = ti * 32, J = tj * 32;
    bool act = (lsort[I] <= lsort[J + 31]) && (lsort[J] <= lsort[I + 31]);
    if (act) {
        int k = atomicAdd(tcnt, 1);
        tlist[k] = (ti << 16) | tj;
    }
}

// ---------------- sparse edge kernel -----------------------------------------
__global__ __launch_bounds__(128) void edge_sparse(
    const float* __restrict__ hi, const float* __restrict__ hjb,
    const float* __restrict__ We2, const float* __restrict__ bwe2,
    const int* __restrict__ lsort,
    const float* __restrict__ ci, const float* __restrict__ dj,
    const int* __restrict__ tlist, const int* __restrict__ tcnt,
    float* __restrict__ E) {
    __shared__ float2 sa[2][32][16];
    __shared__ float2 sb[2][32][16];
    __shared__ float sw[256];

    const int t = threadIdx.x;
    const int tx = t & 15;
    const int ty = t >> 4;
    sw[t] = 0.5f * We2[t];
    sw[t + 128] = 0.5f * We2[t + 128];
    const int n = tcnt[0];
    const float bw = bwe2[0];

    for (int w = blockIdx.x; w < n; w += gridDim.x) {
        const int tile = tlist[w];
        const int I = (tile >> 16) * 32;
        const int J = (tile & 0xffff) * 32;

        auto stage = [&](int c) {
            const int buf = c & 1;
            const int hoff = c * 32;
#pragma unroll
            for (int k = 0; k < 8; k++) {
                int p = t + k * 128;
                if (p < 512) {
                    int r = p >> 4, c2 = p & 15;
                    cp8(&sa[buf][r][c2 ^ (r & 15)],
                        hi + (size_t)(I + r) * H + hoff + c2 * 2);
                } else {
                    int q = p - 512;
                    int r = q >> 4, c2 = q & 15;
                    cp8(&sb[buf][r][c2 ^ (r & 15)],
                        hjb + (size_t)(J + r) * H + hoff + c2 * 2);
                }
            }
        };

        u64 acc[4][2];
#pragma unroll
        for (int m = 0; m < 4; m++)
#pragma unroll
            for (int nn2 = 0; nn2 < 2; nn2++) acc[m][nn2] = 0ull;

        stage(0);
        cp_commit();

        for (int c = 0; c < 8; c++) {
            if (c < 7) {
                stage(c + 1);
                cp_commit();
                cp_wait<1>();
            } else {
                cp_wait<0>();
            }
            __syncthreads();
            const int buf = c & 1;
            const float* swc = &sw[c * 32];
#pragma unroll
            for (int hp = 0; hp < 16; hp++) {
                u64 wv = *(const u64*)&swc[hp * 2];
                u64 aP[4], bP[2];
#pragma unroll
                for (int m = 0; m < 4; m++) {
                    const int r = ty + m * 8;
                    aP[m] = *(const u64*)&sa[buf][r][hp ^ (r & 15)];
                }
#pragma unroll
                for (int nn2 = 0; nn2 < 2; nn2++) {
                    const int r = tx + nn2 * 16;
                    bP[nn2] = *(const u64*)&sb[buf][r][hp ^ (r & 15)];
                }
#pragma unroll
                for (int m = 0; m < 4; m++)
#pragma unroll
                    for (int nn2 = 0; nn2 < 2; nn2++) {
                        u64 s = add2(aP[m], bP[nn2]) & 0x7FFFFFFF7FFFFFFFull;
                        fma2(acc[m][nn2], s, wv);
                    }
            }
            __syncthreads();
        }

#pragma unroll
        for (int m = 0; m < 4; m++) {
            const int i = I + ty + m * 8;
            const int la = lsort[i];
            const float cv = ci[i] + bw;
#pragma unroll
            for (int nn2 = 0; nn2 < 2; nn2++) {
                const int j = J + tx + nn2 * 16;
                float2 p = unpack2(acc[m][nn2]);
                float logit = p.x + p.y + cv + dj[j];
                float e = (la == lsort[j] && i != j)
                              ? 1.f / (1.f + __expf(-logit)) : 0.f;
                E[(size_t)i * NN + j] = e;
            }
        }
    }
}

// ---------------- final: wsum inline; out[perm[p]] = diP[p] + R[p]/wsum -----
__global__ void reduce_final(const float* __restrict__ P, const float* __restrict__ E,
                             const float* __restrict__ diP, const int* __restrict__ perm,
                             float* __restrict__ out) {
    const int t = threadIdx.x;
    const int rg = t >> 6;
    const int c4 = t & 63;
    const int p = blockIdx.x * 4 + rg;

    float s = 0.f;
    const float4* Er = (const float4*)(E + (size_t)p * NN);
#pragma unroll
    for (int e = 0; e < 4; e++) {
        float4 v = Er[c4 + e * 64];
        s += v.x + v.y + v.z + v.w;
    }
#pragma unroll
    for (int o = 16; o > 0; o >>= 1) s += __shfl_xor_sync(~0u, s, o);
    __shared__ float sm[8];
    if ((t & 31) == 0) sm[t >> 5] = s;
    __syncthreads();
    const float w = sm[rg * 2] + sm[rg * 2 + 1];
    const float inv = w > 0.f ? 1.f / w : 0.f;

    const size_t idx = (size_t)p * 64 + c4;
    float4 a = ((const float4*)P)[idx];
    float4 d = ((const float4*)diP)[idx];
    float4 o;
    o.x = fmaf(a.x, inv, d.x);
    o.y = fmaf(a.y, inv, d.y);
    o.z = fmaf(a.z, inv, d.z);
    o.w = fmaf(a.w, inv, d.w);
    ((float4*)out)[(size_t)perm[p] * 64 + c4] = o;
}

// ---------------- launch -----------------------------------------------------
extern "C" void kernel_launch(void* const* d_in, const int* in_sizes, int n_in,
                              void* d_out, int out_size) {
    const float* features = (const float*)d_in[0];
    const int* labels = (const int*)d_in[1];
    const float* W1 = (const float*)d_in[2];
    const float* b1 = (const float*)d_in[3];
    const float* g1 = (const float*)d_in[4];
    const float* bt1 = (const float*)d_in[5];
    const float* W2 = (const float*)d_in[6];
    const float* b2 = (const float*)d_in[7];
    const float* g2 = (const float*)d_in[8];
    const float* bt2 = (const float*)d_in[9];
    const float* We1 = (const float*)d_in[10];
    const float* bwe1 = (const float*)d_in[11];
    const float* We2 = (const float*)d_in[12];
    const float* bwe2 = (const float*)d_in[13];
    float* out = (float*)d_out;

    void *pP, *pQ, *pX1, *pX2, *phij, *pdiP, *pE, *pS;
    void *psc1, *psh1, *psc2, *psh2, *pci, *pdj;
    void *ppos, *pperm, *plsort, *pcls, *ptlist, *ptcnt;
    cudaGetSymbolAddress(&pP, g_P);
    cudaGetSymbolAddress(&pQ, g_Q);
    cudaGetSymbolAddress(&pX1, g_X1);
    cudaGetSymbolAddress(&pX2, g_X2);
    cudaGetSymbolAddress(&phij, g_hij);
    cudaGetSymbolAddress(&pdiP, g_diP);
    cudaGetSymbolAddress(&pE, g_E);
    cudaGetSymbolAddress(&pS, g_S);
    cudaGetSymbolAddress(&psc1, g_sc1);
    cudaGetSymbolAddress(&psh1, g_sh1);
    cudaGetSymbolAddress(&psc2, g_sc2);
    cudaGetSymbolAddress(&psh2, g_sh2);
    cudaGetSymbolAddress(&pci, g_ci);
    cudaGetSymbolAddress(&pdj, g_dj);
    cudaGetSymbolAddress(&ppos, g_pos);
    cudaGetSymbolAddress(&pperm, g_perm);
    cudaGetSymbolAddress(&plsort, g_lsort);
    cudaGetSymbolAddress(&pcls, g_cls);
    cudaGetSymbolAddress(&ptlist, g_tlist);
    cudaGetSymbolAddress(&ptcnt, g_tcnt);

    float* P = (float*)pP;
    float* Q = (float*)pQ;
    float* X1 = (float*)pX1;
    float* X2 = (float*)pX2;
    float* hij = (float*)phij;
    float* diP = (float*)pdiP;
    float* E = (float*)pE;
    float* S = (float*)pS;
    float* sc1 = (float*)psc1;
    float* sh1 = (float*)psh1;
    float* sc2 = (float*)psc2;
    float* sh2 = (float*)psh2;
    float* ci = (float*)pci;
    float* dj = (float*)pdj;
    int* pos = (int*)ppos;
    int* perm = (int*)pperm;
    int* lsort = (int*)plsort;
    int* cls = (int*)pcls;
    int* tlist = (int*)ptlist;
    int* tcnt = (int*)ptcnt;

    // 0) label ranking / permutation / tile worklist
    rank_kernel<<<8, 128>>>(labels, pos, perm, lsort, cls, tcnt);
    zero_E<<<1024, 256>>>(E);
    build_worklist<<<1, 1024>>>(lsort, tlist, tcnt);

    // 1) GEMM1: features @ W1, split-K8 -> P planes 0..7
    gemm_k<false, false><<<dim3(4, 32, 8), 128>>>(
        features, W1, P, 2048, 256, nullptr, nullptr);
    // 2) X1 = sum(P)+b1; BN1 stats
    stats_phase1<8><<<256, 256>>>(P, b1, X1, S);
    stats_phase2<<<8, 256>>>(S, g1, bt1, sc1, sh1);
    // 3) GEMM2: relu(BN1(X1)) @ W2 (BNA), split-K4 -> Q planes 0..3
    gemm_k<false, true><<<dim3(4, 32, 4), 128>>>(
        X1, W2, Q, 256, 64, sc1, sh1);
    // 4) X2 = sum(Q)+b2; BN2 stats
    stats_phase1<4><<<256, 256>>>(Q, b2, X2, S);
    stats_phase2<<<8, 256>>>(S, g2, bt2, sc2, sh2);
    // 5) diP[pos[r]] = relu(BN2(X2[r]))
    apply_relu_perm<<<256, 256>>>(X2, sc2, sh2, pos, diP);
    // 6) GEMM3: di @ We1 dual halves (BNA from X2), split-K2 -> Q planes 0..3
    gemm_k<true, true><<<dim3(4, 32, 4), 128>>>(
        X2, We1, Q, 256, 128, sc2, sh2);
    // 7) combine -> hi/hjb permuted (+bwe1), ci/dj permuted
    combine_cidj<<<NN, 256>>>(Q, bwe1, We2, pos, hij, hij + (size_t)NN * H, ci, dj);
    // 8) sparse edge weights (active tiles only)
    edge_sparse<<<296, 128>>>(hij, hij + (size_t)NN * H, We2, bwe2, lsort,
                              ci, dj, tlist, tcnt, E);
    // 9) GEMM4: E @ diP over per-tile class k-range -> P plane 0
    gemm4_range<<<dim3(4, 32), 128>>>(E, diP, lsort, cls, P);
    // 10) out[perm[p]] = diP[p] + R[p]/wsum[p]
    reduce_final<<<256, 256>>>(P, E, diP, perm, out);
}